// round 14
// baseline (speedup 1.0000x reference)
#include <cuda_runtime.h>
#include <cuda_bf16.h>

// FINAL (held). The reference network mathematically collapses: the GNN
// "layernorm" is over a feature axis of size 1, so (y-mean)/sqrt(var+eps)==0
// exactly and h == ln_bias[l] after each propagation layer, independent of
// everything upstream (hash grids, SIREN trunk, member heads, 2M graph edges).
// Output = softplus(ln_bias[1,0]) * sigmoid((1 - psi_n) * 50), elementwise.
//
// Measurement model (R1-R13, eight benches of byte-identical source):
//   bench: BIMODAL — common mode ~4.55us (4.512, 4.544 x3, 4.576 x2, 4.608),
//   occasional mode ~6.9us (6.880); within-mode sigma ~0.03us.
//   ncu kernel-internal: 3.78-4.35us across 13 profiles, every pipe <1% —
//   pure launch-overhead floor (T_ovh ~5000cyc + one DRAM round-trip).
// Shape/body space fully characterized; no .cu-level lever moves either mode.
// Pinned configuration: 256 CTAs x 64 thr, __expf/__fdividef body, 16 regs.

__global__ __launch_bounds__(64, 32)
void collapsed_forward_kernel(const float* __restrict__ psi_n,
                              const float* __restrict__ ln_bias,
                              float* __restrict__ out) {
    int i = blockIdx.x * 64 + threadIdx.x;   // exactly 16384 threads = n/4

    // Issue both loads immediately so their DRAM latencies overlap.
    float4 p = reinterpret_cast<const float4*>(psi_n)[i];
    float b = __ldg(&ln_bias[1]);

    float refined = __logf(1.0f + __expf(b));   // softplus(ln_bias[1])

    // refined * sigmoid((1-p)*50); sigmoid arg negated: (p-1)*50 = fma(p,50,-50)
    float4 r;
    r.x = __fdividef(refined, 1.0f + __expf(fmaf(p.x, 50.0f, -50.0f)));
    r.y = __fdividef(refined, 1.0f + __expf(fmaf(p.y, 50.0f, -50.0f)));
    r.z = __fdividef(refined, 1.0f + __expf(fmaf(p.z, 50.0f, -50.0f)));
    r.w = __fdividef(refined, 1.0f + __expf(fmaf(p.w, 50.0f, -50.0f)));
    reinterpret_cast<float4*>(out)[i] = r;
}

extern "C" void kernel_launch(void* const* d_in, const int* in_sizes, int n_in,
                              void* d_out, int out_size) {
    const float* psi_n   = (const float*)d_in[2];
    const float* ln_bias = (const float*)d_in[25];
    float* out = (float*)d_out;

    int n4 = out_size / 4;          // 16384
    int blocks = n4 / 64;           // 256 CTAs x 64 threads, exact cover
    collapsed_forward_kernel<<<blocks, 64>>>(psi_n, ln_bias, out);
}

// round 15
// speedup vs baseline: 1.5105x; 1.5105x over previous
#include <cuda_runtime.h>
#include <cuda_bf16.h>

// FINAL (held). The reference network mathematically collapses: the GNN
// "layernorm" is over a feature axis of size 1, so (y-mean)/sqrt(var+eps)==0
// exactly and h == ln_bias[l] after each propagation layer, independent of
// everything upstream (hash grids, SIREN trunk, member heads, 2M graph edges).
// Output = softplus(ln_bias[1,0]) * sigmoid((1 - psi_n) * 50), elementwise.
//
// Measurement model (R1-R14, nine benches of byte-identical source):
//   bench: BIMODAL — fast mode ~4.55us x7 (4.512, 4.544 x3, 4.576 x2, 4.608),
//   slow mode ~6.9us x2 (6.880, 6.912); within-mode sigma ~0.03us. The mode
//   draw does not correlate with any kernel property (same binary produced
//   both; ncu kernel time was ~4.3-4.5us on both draws).
//   ncu kernel-internal: 3.78-4.51us across 14 profiles, every pipe <1% —
//   pure launch-overhead floor (T_ovh ~5000cyc + one DRAM round-trip).
// No .cu-level lever exists for either the floor or the mode. Pinned
// configuration: 256 CTAs x 64 thr, __expf/__fdividef body, 16 regs.

__global__ __launch_bounds__(64, 32)
void collapsed_forward_kernel(const float* __restrict__ psi_n,
                              const float* __restrict__ ln_bias,
                              float* __restrict__ out) {
    int i = blockIdx.x * 64 + threadIdx.x;   // exactly 16384 threads = n/4

    // Issue both loads immediately so their DRAM latencies overlap.
    float4 p = reinterpret_cast<const float4*>(psi_n)[i];
    float b = __ldg(&ln_bias[1]);

    float refined = __logf(1.0f + __expf(b));   // softplus(ln_bias[1])

    // refined * sigmoid((1-p)*50); sigmoid arg negated: (p-1)*50 = fma(p,50,-50)
    float4 r;
    r.x = __fdividef(refined, 1.0f + __expf(fmaf(p.x, 50.0f, -50.0f)));
    r.y = __fdividef(refined, 1.0f + __expf(fmaf(p.y, 50.0f, -50.0f)));
    r.z = __fdividef(refined, 1.0f + __expf(fmaf(p.z, 50.0f, -50.0f)));
    r.w = __fdividef(refined, 1.0f + __expf(fmaf(p.w, 50.0f, -50.0f)));
    reinterpret_cast<float4*>(out)[i] = r;
}

extern "C" void kernel_launch(void* const* d_in, const int* in_sizes, int n_in,
                              void* d_out, int out_size) {
    const float* psi_n   = (const float*)d_in[2];
    const float* ln_bias = (const float*)d_in[25];
    float* out = (float*)d_out;

    int n4 = out_size / 4;          // 16384
    int blocks = n4 / 64;           // 256 CTAs x 64 threads, exact cover
    collapsed_forward_kernel<<<blocks, 64>>>(psi_n, ln_bias, out);
}

// round 16
// speedup vs baseline: 1.5211x; 1.0070x over previous
#include <cuda_runtime.h>
#include <cuda_bf16.h>

// FINAL (held, terminal). The reference network mathematically collapses: the
// GNN "layernorm" is over a feature axis of size 1, so
// (y-mean)/sqrt(var+eps)==0 exactly and h == ln_bias[l] after each
// propagation layer, independent of everything upstream (hash grids, SIREN
// trunk, member heads, 2M graph edges).
// Output = softplus(ln_bias[1,0]) * sigmoid((1 - psi_n) * 50), elementwise.
//
// Session evidence (R1-R15; ten benches of byte-identical source):
//   bench: BIMODAL — fast mode ~4.55us x8 (4.512 .. 4.608), slow mode ~6.9us
//   x2 (6.880, 6.912); within-mode sigma ~0.03us; mode uncorrelated with any
//   kernel property (same binary produced both).
//   ncu kernel-internal: 3.78-4.51us across 15 profiles, every pipe <1%,
//   DRAM <=0.9% — pure launch-overhead floor (T_ovh ~5000cyc + one DRAM
//   round-trip), invariant across 3 body variants x 4 grid shapes.
// The collapse itself (~100x vs a faithful pipeline) was the optimization;
// no .cu-level lever remains for the floor or the mode. Pinned configuration:
// 256 CTAs x 64 thr, one float4/thread, __expf/__fdividef body, 16 regs.

__global__ __launch_bounds__(64, 32)
void collapsed_forward_kernel(const float* __restrict__ psi_n,
                              const float* __restrict__ ln_bias,
                              float* __restrict__ out) {
    int i = blockIdx.x * 64 + threadIdx.x;   // exactly 16384 threads = n/4

    // Issue both loads immediately so their DRAM latencies overlap.
    float4 p = reinterpret_cast<const float4*>(psi_n)[i];
    float b = __ldg(&ln_bias[1]);

    float refined = __logf(1.0f + __expf(b));   // softplus(ln_bias[1])

    // refined * sigmoid((1-p)*50); sigmoid arg negated: (p-1)*50 = fma(p,50,-50)
    float4 r;
    r.x = __fdividef(refined, 1.0f + __expf(fmaf(p.x, 50.0f, -50.0f)));
    r.y = __fdividef(refined, 1.0f + __expf(fmaf(p.y, 50.0f, -50.0f)));
    r.z = __fdividef(refined, 1.0f + __expf(fmaf(p.z, 50.0f, -50.0f)));
    r.w = __fdividef(refined, 1.0f + __expf(fmaf(p.w, 50.0f, -50.0f)));
    reinterpret_cast<float4*>(out)[i] = r;
}

extern "C" void kernel_launch(void* const* d_in, const int* in_sizes, int n_in,
                              void* d_out, int out_size) {
    const float* psi_n   = (const float*)d_in[2];
    const float* ln_bias = (const float*)d_in[25];
    float* out = (float*)d_out;

    int n4 = out_size / 4;          // 16384
    int blocks = n4 / 64;           // 256 CTAs x 64 threads, exact cover
    collapsed_forward_kernel<<<blocks, 64>>>(psi_n, ln_bias, out);
}